// round 4
// baseline (speedup 1.0000x reference)
#include <cuda_runtime.h>

#define HID    4096
#define GATES  (3*HID)
#define NVOCAB 256
#define TPB    256
#define NWARP  8
#define NBLK_PER_SM 6
#define GRID   (148 * NBLK_PER_SM)   // 888 — all co-resident by launch_bounds
#define SEGN   (GRID / 3)            // 296 blocks per matrix in phase A
#define NTILE  (GATES / NWARP)       // 1536 row-tiles per 12288-row matrix

// Scratch + sync (allocation-free rule: __device__ globals).
__device__ float g_gi0[GATES];
__device__ float g_gh0[GATES];
__device__ float g_gh1[GATES];
__device__ float g_gi1[GATES];
__device__ float g_h0[HID];
__device__ float g_h1[HID];
__device__ unsigned g_bar[4];   // monotonic ticket counters (replay-safe, never reset)

__device__ __forceinline__ float sigmoidf_(float v) {
    return 1.0f / (1.0f + __expf(-v));
}

// Grid-wide barrier: monotonic counter, target = next multiple of GRID past my
// ticket. Correct across unlimited graph replays without any reset.
__device__ __forceinline__ void grid_barrier(int k) {
    __syncthreads();
    if (threadIdx.x == 0) {
        __threadfence();                       // publish my block's writes
        unsigned ticket = atomicAdd(&g_bar[k], 1u);
        unsigned target = (ticket / (unsigned)GRID + 1u) * (unsigned)GRID;
        while (*((volatile unsigned*)&g_bar[k]) < target) {
            __nanosleep(64);
        }
        __threadfence();                       // acquire side
    }
    __syncthreads();
}

// Warp computes dot(W[row,:], sx[:]) over HID=4096 (lane-strided float4).
__device__ __forceinline__ float warp_dot_row(const float4* __restrict__ w4,
                                              const float4* __restrict__ sx4,
                                              int lane) {
    float acc = 0.0f;
    #pragma unroll
    for (int i = 0; i < HID / 4 / 32; i++) {   // 32 iterations
        float4 a  = w4[lane + 32 * i];
        float4 xv = sx4[lane + 32 * i];
        acc += a.x * xv.x + a.y * xv.y + a.z * xv.z + a.w * xv.w;
    }
    #pragma unroll
    for (int off = 16; off; off >>= 1)
        acc += __shfl_down_sync(0xffffffffu, acc, off);
    return acc;
}

__global__ __launch_bounds__(TPB, NBLK_PER_SM) void gru_step_kernel(
    const int*   __restrict__ inp,  const float* __restrict__ hidden,
    const float* __restrict__ emb,
    const float* __restrict__ Wih0, const float* __restrict__ Whh0,
    const float* __restrict__ bih0, const float* __restrict__ bhh0,
    const float* __restrict__ Wih1, const float* __restrict__ Whh1,
    const float* __restrict__ bih1, const float* __restrict__ bhh1,
    const float* __restrict__ Wdec, const float* __restrict__ bdec,
    float* __restrict__ out)
{
    __shared__ float sx[HID];
    const int bid  = blockIdx.x;
    const int tid  = threadIdx.x;
    const int warp = tid >> 5;
    const int lane = tid & 31;

    // ================= Phase A: gi0 / gh0 / gh1 (3 x 201 MB streamed) ======
    {
        const int seg     = bid / SEGN;          // 0,1,2
        const int segblk  = bid - seg * SEGN;
        const float *W, *b, *x;
        float *y;
        if (seg == 0)      { W = Wih0; b = bih0; x = emb + (size_t)inp[0] * HID; y = g_gi0; }
        else if (seg == 1) { W = Whh0; b = bhh0; x = hidden;                     y = g_gh0; }
        else               { W = Whh1; b = bhh1; x = hidden + HID;               y = g_gh1; }

        for (int i = tid; i < HID / 4; i += TPB)
            ((float4*)sx)[i] = ((const float4*)x)[i];
        __syncthreads();

        for (int t = segblk; t < NTILE; t += SEGN) {
            const int row = t * NWARP + warp;
            float acc = warp_dot_row((const float4*)(W + (size_t)row * HID),
                                     (const float4*)sx, lane);
            if (lane == 0) y[row] = acc + b[row];
        }
    }
    grid_barrier(0);

    // ================= Phase B: gate0 -> h0_new ============================
    {
        const int g = bid * TPB + tid;
        if (g < HID) {
            float r = sigmoidf_(__ldcg(&g_gi0[g])         + __ldcg(&g_gh0[g]));
            float z = sigmoidf_(__ldcg(&g_gi0[g + HID])   + __ldcg(&g_gh0[g + HID]));
            float n = tanhf    (__ldcg(&g_gi0[g + 2*HID]) + r * __ldcg(&g_gh0[g + 2*HID]));
            float h = (1.0f - z) * n + z * hidden[g];
            g_h0[g] = h;
            out[NVOCAB + g] = h;                 // new_h[0]
        }
    }
    grid_barrier(1);

    // ================= Phase C: gi1 = W_ih1 @ h0_new (201 MB) ==============
    {
        __syncthreads();                          // sx reuse safety
        for (int i = tid; i < HID / 4; i += TPB)
            ((float4*)sx)[i] = __ldcg(((const float4*)g_h0) + i);
        __syncthreads();

        for (int t = bid; t < NTILE; t += GRID) {
            const int row = t * NWARP + warp;
            float acc = warp_dot_row((const float4*)(Wih1 + (size_t)row * HID),
                                     (const float4*)sx, lane);
            if (lane == 0) g_gi1[row] = acc + bih1[row];
        }
    }
    grid_barrier(2);

    // ================= Phase D: gate1 -> h1_new ============================
    {
        const int g = bid * TPB + tid;
        if (g < HID) {
            float r = sigmoidf_(__ldcg(&g_gi1[g])         + __ldcg(&g_gh1[g]));
            float z = sigmoidf_(__ldcg(&g_gi1[g + HID])   + __ldcg(&g_gh1[g + HID]));
            float n = tanhf    (__ldcg(&g_gi1[g + 2*HID]) + r * __ldcg(&g_gh1[g + 2*HID]));
            float h = (1.0f - z) * n + z * hidden[HID + g];
            g_h1[g] = h;
            out[NVOCAB + HID + g] = h;           // new_h[1]
        }
    }
    grid_barrier(3);

    // ================= Phase E: decoder logits (4 MB, 32 blocks) ===========
    if (bid < NVOCAB / NWARP) {
        __syncthreads();
        for (int i = tid; i < HID / 4; i += TPB)
            ((float4*)sx)[i] = __ldcg(((const float4*)g_h1) + i);
        __syncthreads();

        const int row = bid * NWARP + warp;
        float acc = warp_dot_row((const float4*)(Wdec + (size_t)row * HID),
                                 (const float4*)sx, lane);
        if (lane == 0) out[row] = acc + bdec[row];
    }
}

// ---------------------------------------------------------------------------
// Inputs (metadata order):
// 0 inp(int32,1) 1 hidden(2*4096) 2 emb(256*4096)
// 3 W_ih0 4 W_hh0 5 b_ih0 6 b_hh0
// 7 W_ih1 8 W_hh1 9 b_ih1 10 b_hh1
// 11 W_dec 12 b_dec
// Output: [logits(256) | h0_new(4096) | h1_new(4096)]
// ---------------------------------------------------------------------------
extern "C" void kernel_launch(void* const* d_in, const int* in_sizes, int n_in,
                              void* d_out, int out_size)
{
    const int*   inp    = (const int*)  d_in[0];
    const float* hidden = (const float*)d_in[1];
    const float* emb    = (const float*)d_in[2];
    const float* Wih0   = (const float*)d_in[3];
    const float* Whh0   = (const float*)d_in[4];
    const float* bih0   = (const float*)d_in[5];
    const float* bhh0   = (const float*)d_in[6];
    const float* Wih1   = (const float*)d_in[7];
    const float* Whh1   = (const float*)d_in[8];
    const float* bih1   = (const float*)d_in[9];
    const float* bhh1   = (const float*)d_in[10];
    const float* Wdec   = (const float*)d_in[11];
    const float* bdec   = (const float*)d_in[12];
    float* out = (float*)d_out;

    gru_step_kernel<<<GRID, TPB>>>(inp, hidden, emb,
                                   Wih0, Whh0, bih0, bhh0,
                                   Wih1, Whh1, bih1, bhh1,
                                   Wdec, bdec, out);
}

// round 5
// speedup vs baseline: 2.2393x; 2.2393x over previous
#include <cuda_runtime.h>

#define HID 4096
#define GATES (3*HID)
#define NVOCAB 256
#define ROWS_PER_BLOCK 8   // 8 warps, warp-per-row

// Scratch (allocation-free rule: __device__ globals). 16B-aligned for float4.
__device__ __align__(16) float g_gi0[GATES];
__device__ __align__(16) float g_gh0[GATES];
__device__ __align__(16) float g_gh1[GATES];
__device__ __align__(16) float g_gi1[GATES];
__device__ __align__(16) float g_h0[HID];
__device__ __align__(16) float g_h1[HID];

__device__ __forceinline__ float sigmoidf_(float v) {
    return 1.0f / (1.0f + __expf(-v));
}

// Warp dot over HID=4096; weights streamed with evict-first (__ldcs) so the
// small scratch/x vectors stay L2-resident.
__device__ __forceinline__ float warp_dot_row(const float4* __restrict__ w4,
                                              const float4* __restrict__ sx4,
                                              int lane) {
    float acc = 0.0f;
    #pragma unroll
    for (int i = 0; i < HID / 4 / 32; i++) {       // 32 iterations
        float4 a  = __ldcs(w4 + lane + 32 * i);
        float4 xv = sx4[lane + 32 * i];
        acc += a.x * xv.x + a.y * xv.y + a.z * xv.z + a.w * xv.w;
    }
    #pragma unroll
    for (int off = 16; off; off >>= 1)
        acc += __shfl_down_sync(0xffffffffu, acc, off);
    return acc;
}

// ---------------------------------------------------------------------------
// Fused 3-matrix matvec: gi0 = W_ih0 @ emb[inp] + b_ih0
//                        gh0 = W_hh0 @ h[0]     + b_hh0
//                        gh1 = W_hh1 @ h[1]     + b_hh1
// Warp-per-row. Grid = 3 * 1536 = 4608 blocks.
// ---------------------------------------------------------------------------
__global__ __launch_bounds__(256) void mv3_kernel(
    const int* __restrict__ inp, const float* __restrict__ hidden,
    const float* __restrict__ emb,
    const float* __restrict__ Wih0, const float* __restrict__ Whh0,
    const float* __restrict__ Whh1,
    const float* __restrict__ bih0, const float* __restrict__ bhh0,
    const float* __restrict__ bhh1)
{
    __shared__ float sx[HID];
    const int warp = threadIdx.x >> 5;
    const int lane = threadIdx.x & 31;

    const int blocks_per_seg = GATES / ROWS_PER_BLOCK;   // 1536
    const int seg    = blockIdx.x / blocks_per_seg;      // 0,1,2
    const int segblk = blockIdx.x % blocks_per_seg;

    const float* W; const float* b; const float* x; float* y;
    if (seg == 0)      { W = Wih0; b = bih0; x = emb + (size_t)inp[0] * HID; y = g_gi0; }
    else if (seg == 1) { W = Whh0; b = bhh0; x = hidden;                     y = g_gh0; }
    else               { W = Whh1; b = bhh1; x = hidden + HID;               y = g_gh1; }

    for (int i = threadIdx.x; i < HID / 4; i += blockDim.x)
        ((float4*)sx)[i] = ((const float4*)x)[i];
    __syncthreads();

    const int row = segblk * ROWS_PER_BLOCK + warp;
    float acc = warp_dot_row((const float4*)(W + (size_t)row * HID),
                             (const float4*)sx, lane);
    if (lane == 0) y[row] = acc + b[row];
}

// ---------------------------------------------------------------------------
// Single-matrix matvec: gi1 = W_ih1 @ g_h0 + b_ih1.  Grid = 1536 blocks.
// ---------------------------------------------------------------------------
__global__ __launch_bounds__(256) void mv1_kernel(
    const float* __restrict__ Wih1, const float* __restrict__ bih1)
{
    __shared__ float sx[HID];
    const int warp = threadIdx.x >> 5;
    const int lane = threadIdx.x & 31;

    for (int i = threadIdx.x; i < HID / 4; i += blockDim.x)
        ((float4*)sx)[i] = ((const float4*)g_h0)[i];
    __syncthreads();

    const int row = blockIdx.x * ROWS_PER_BLOCK + warp;
    float acc = warp_dot_row((const float4*)(Wih1 + (size_t)row * HID),
                             (const float4*)sx, lane);
    if (lane == 0) g_gi1[row] = acc + bih1[row];
}

// ---------------------------------------------------------------------------
// GRU gate math, vectorized float4: 1024 threads, 8 blocks x 128.
// layer = 0: gi=g_gi0, gh=g_gh0, h_prev=hidden[0], h_out=g_h0, out+NVOCAB
// ---------------------------------------------------------------------------
__global__ __launch_bounds__(128) void gate0_kernel(
    const float* __restrict__ hidden, float* __restrict__ out)
{
    const int j4 = blockIdx.x * blockDim.x + threadIdx.x;   // 0..1023
    if (j4 >= HID / 4) return;
    const float4* gi = (const float4*)g_gi0;
    const float4* gh = (const float4*)g_gh0;
    float4 ir = gi[j4];
    float4 hr = gh[j4];
    float4 iz = gi[j4 + HID/4];
    float4 hz = gh[j4 + HID/4];
    float4 in_ = gi[j4 + 2*(HID/4)];
    float4 hn  = gh[j4 + 2*(HID/4)];
    float4 hp = ((const float4*)hidden)[j4];
    float4 h;
    {
        float r = sigmoidf_(ir.x + hr.x), z = sigmoidf_(iz.x + hz.x);
        float n = tanhf(in_.x + r * hn.x); h.x = (1.0f - z) * n + z * hp.x;
    }
    {
        float r = sigmoidf_(ir.y + hr.y), z = sigmoidf_(iz.y + hz.y);
        float n = tanhf(in_.y + r * hn.y); h.y = (1.0f - z) * n + z * hp.y;
    }
    {
        float r = sigmoidf_(ir.z + hr.z), z = sigmoidf_(iz.z + hz.z);
        float n = tanhf(in_.z + r * hn.z); h.z = (1.0f - z) * n + z * hp.z;
    }
    {
        float r = sigmoidf_(ir.w + hr.w), z = sigmoidf_(iz.w + hz.w);
        float n = tanhf(in_.w + r * hn.w); h.w = (1.0f - z) * n + z * hp.w;
    }
    ((float4*)g_h0)[j4] = h;
    ((float4*)(out + NVOCAB))[j4] = h;           // new_h[0]
}

__global__ __launch_bounds__(128) void gate1_kernel(
    const float* __restrict__ hidden, float* __restrict__ out)
{
    const int j4 = blockIdx.x * blockDim.x + threadIdx.x;
    if (j4 >= HID / 4) return;
    const float4* gi = (const float4*)g_gi1;
    const float4* gh = (const float4*)g_gh1;
    float4 ir = gi[j4];
    float4 hr = gh[j4];
    float4 iz = gi[j4 + HID/4];
    float4 hz = gh[j4 + HID/4];
    float4 in_ = gi[j4 + 2*(HID/4)];
    float4 hn  = gh[j4 + 2*(HID/4)];
    float4 hp = ((const float4*)(hidden + HID))[j4];
    float4 h;
    {
        float r = sigmoidf_(ir.x + hr.x), z = sigmoidf_(iz.x + hz.x);
        float n = tanhf(in_.x + r * hn.x); h.x = (1.0f - z) * n + z * hp.x;
    }
    {
        float r = sigmoidf_(ir.y + hr.y), z = sigmoidf_(iz.y + hz.y);
        float n = tanhf(in_.y + r * hn.y); h.y = (1.0f - z) * n + z * hp.y;
    }
    {
        float r = sigmoidf_(ir.z + hr.z), z = sigmoidf_(iz.z + hz.z);
        float n = tanhf(in_.z + r * hn.z); h.z = (1.0f - z) * n + z * hp.z;
    }
    {
        float r = sigmoidf_(ir.w + hr.w), z = sigmoidf_(iz.w + hz.w);
        float n = tanhf(in_.w + r * hn.w); h.w = (1.0f - z) * n + z * hp.w;
    }
    ((float4*)g_h1)[j4] = h;
    ((float4*)(out + NVOCAB + HID))[j4] = h;     // new_h[1]
}

// ---------------------------------------------------------------------------
// Decoder: out[0:256] = W_dec @ h1_new + b_dec.  Grid = 32 blocks.
// ---------------------------------------------------------------------------
__global__ __launch_bounds__(256) void dec_kernel(
    const float* __restrict__ Wdec, const float* __restrict__ bdec,
    float* __restrict__ out)
{
    __shared__ float sx[HID];
    const int warp = threadIdx.x >> 5;
    const int lane = threadIdx.x & 31;

    for (int i = threadIdx.x; i < HID / 4; i += blockDim.x)
        ((float4*)sx)[i] = ((const float4*)g_h1)[i];
    __syncthreads();

    const int row = blockIdx.x * ROWS_PER_BLOCK + warp;
    float acc = warp_dot_row((const float4*)(Wdec + (size_t)row * HID),
                             (const float4*)sx, lane);
    if (lane == 0) out[row] = acc + bdec[row];
}

// ---------------------------------------------------------------------------
// Inputs (metadata order):
// 0 inp(int32,1) 1 hidden(2*4096) 2 emb(256*4096)
// 3 W_ih0 4 W_hh0 5 b_ih0 6 b_hh0
// 7 W_ih1 8 W_hh1 9 b_ih1 10 b_hh1
// 11 W_dec 12 b_dec
// Output: [logits(256) | h0_new(4096) | h1_new(4096)]
// ---------------------------------------------------------------------------
extern "C" void kernel_launch(void* const* d_in, const int* in_sizes, int n_in,
                              void* d_out, int out_size)
{
    const int*   inp    = (const int*)  d_in[0];
    const float* hidden = (const float*)d_in[1];
    const float* emb    = (const float*)d_in[2];
    const float* Wih0   = (const float*)d_in[3];
    const float* Whh0   = (const float*)d_in[4];
    const float* bih0   = (const float*)d_in[5];
    const float* bhh0   = (const float*)d_in[6];
    const float* Wih1   = (const float*)d_in[7];
    const float* Whh1   = (const float*)d_in[8];
    const float* bih1   = (const float*)d_in[9];
    const float* bhh1   = (const float*)d_in[10];
    const float* Wdec   = (const float*)d_in[11];
    const float* bdec   = (const float*)d_in[12];
    float* out = (float*)d_out;

    const int mv_blocks = GATES / ROWS_PER_BLOCK;   // 1536 per matrix
    const int gate_blocks = (HID / 4) / 128;        // 8 blocks

    mv3_kernel<<<3 * mv_blocks, 256>>>(inp, hidden, emb, Wih0, Whh0, Whh1,
                                       bih0, bhh0, bhh1);
    gate0_kernel<<<gate_blocks, 128>>>(hidden, out);
    mv1_kernel<<<mv_blocks, 256>>>(Wih1, bih1);
    gate1_kernel<<<gate_blocks, 128>>>(hidden, out);
    dec_kernel<<<NVOCAB / ROWS_PER_BLOCK, 256>>>(Wdec, bdec, out);
}